// round 2
// baseline (speedup 1.0000x reference)
#include <cuda_runtime.h>
#include <cstdint>

// ----------------------------------------------------------------------------
// BilinearPolicy: two 4-layer MLP trunks + per-action bilinear contraction.
//   obs:   [4096,256] -> 2048 -> 2048 -> 2048 -> 16384   (ReLU on first 3)
//   dlt:   same shapes, separate weights
//   pred[b,a] = sum_f ob[b, a*512+f] * dl[b, f*32+a]
//
// Strategy (round 1): split-tf32 (3xTF32) mma.sync GEMMs for near-fp32
// accuracy; last layer fused with the bilinear reduction so the 2x268MB
// layer-4 outputs are never materialized.
// ----------------------------------------------------------------------------

#define BM 128
#define BN 128
#define BK 32
#define ASTRIDE 36    // smem row stride for A tiles  [BM][ASTRIDE]
#define BSTRIDE 136   // smem row stride for B tiles  [BK][BSTRIDE]
#define SMEM_FLOATS (2 * BM * ASTRIDE + 2 * BK * BSTRIDE)   // 17920 floats = 71680 B

// ------------------------- static device scratch ----------------------------
__device__ float g_t0 [4096 * 2048];            // trunk temp (ping)
__device__ float g_t1 [4096 * 2048];            // trunk temp (pong)
__device__ float g_hob[4096 * 2048];            // obs trunk hidden-3
__device__ float g_hdl[4096 * 2048];            // dlt trunk hidden-3
__device__ float g_WdT[2048ull * 16384ull];     // dlt_W3 rearranged [a][k][f]

// ------------------------------ helpers -------------------------------------
__device__ __forceinline__ void split2(float v, float& hi, float& lo) {
    uint32_t h;
    asm("cvt.rna.tf32.f32 %0, %1;" : "=r"(h) : "f"(v));
    hi = __uint_as_float(h);
    lo = v - hi;                    // exact (hi is v rounded to 10-bit mantissa)
}

__device__ __forceinline__ void mma_tf32(float* c, const uint32_t* a, const uint32_t* b) {
    asm volatile(
        "mma.sync.aligned.m16n8k8.row.col.f32.tf32.tf32.f32 "
        "{%0,%1,%2,%3},{%4,%5,%6,%7},{%8,%9},{%0,%1,%2,%3};"
        : "+f"(c[0]), "+f"(c[1]), "+f"(c[2]), "+f"(c[3])
        : "r"(a[0]), "r"(a[1]), "r"(a[2]), "r"(a[3]), "r"(b[0]), "r"(b[1]));
}

// Computes a [BM x BN] tile of A(row-major, lda) @ B(row-major, ldb) over K,
// accumulating into c[2][8][4] fragments (m16n8k8 layout), with split-tf32
// (hi*hi + lo*hi + hi*lo) for ~fp32 accuracy.
__device__ __forceinline__ void gemm_tile(
    float c[2][8][4],
    const float* __restrict__ A, int lda,
    const float* __restrict__ B, int ldb,
    int K, float* sm)
{
    float* Ah = sm;
    float* Al = Ah + BM * ASTRIDE;
    float* Bh = Al + BM * ASTRIDE;
    float* Bl = Bh + BK * BSTRIDE;

    const int tid  = threadIdx.x;
    const int lane = tid & 31;
    const int wid  = tid >> 5;
    const int wm   = wid & 3;      // 4 warps along M (32 rows each)
    const int wn   = wid >> 2;     // 2 warps along N (64 cols each)

    for (int kt = 0; kt < K; kt += BK) {
        // ---- stage A tile [BM][BK], split into hi/lo -----------------------
        #pragma unroll
        for (int it = 0; it < 4; ++it) {
            int r  = (tid >> 3) + it * 32;
            int kc = (tid & 7) * 4;
            const float4 v = *reinterpret_cast<const float4*>(
                A + (size_t)r * lda + kt + kc);
            int base = r * ASTRIDE + kc;
            split2(v.x, Ah[base + 0], Al[base + 0]);
            split2(v.y, Ah[base + 1], Al[base + 1]);
            split2(v.z, Ah[base + 2], Al[base + 2]);
            split2(v.w, Ah[base + 3], Al[base + 3]);
        }
        // ---- stage B tile [BK][BN], split into hi/lo -----------------------
        #pragma unroll
        for (int it = 0; it < 4; ++it) {
            int idx = tid + it * 256;
            int r   = idx >> 5;
            int nc  = (idx & 31) * 4;
            const float4 v = *reinterpret_cast<const float4*>(
                B + (size_t)(kt + r) * ldb + nc);
            int base = r * BSTRIDE + nc;
            split2(v.x, Bh[base + 0], Bl[base + 0]);
            split2(v.y, Bh[base + 1], Bl[base + 1]);
            split2(v.z, Bh[base + 2], Bl[base + 2]);
            split2(v.w, Bh[base + 3], Bl[base + 3]);
        }
        __syncthreads();

        // ---- compute: 4 k-steps of 8 ---------------------------------------
        #pragma unroll
        for (int ks = 0; ks < BK; ks += 8) {
            uint32_t ah[2][4], al[2][4], bh[8][2], bl[8][2];
            #pragma unroll
            for (int mt = 0; mt < 2; ++mt) {
                int r  = wm * 32 + mt * 16 + (lane >> 2);
                int kk = ks + (lane & 3);
                ah[mt][0] = __float_as_uint(Ah[ r      * ASTRIDE + kk    ]);
                ah[mt][1] = __float_as_uint(Ah[(r + 8) * ASTRIDE + kk    ]);
                ah[mt][2] = __float_as_uint(Ah[ r      * ASTRIDE + kk + 4]);
                ah[mt][3] = __float_as_uint(Ah[(r + 8) * ASTRIDE + kk + 4]);
                al[mt][0] = __float_as_uint(Al[ r      * ASTRIDE + kk    ]);
                al[mt][1] = __float_as_uint(Al[(r + 8) * ASTRIDE + kk    ]);
                al[mt][2] = __float_as_uint(Al[ r      * ASTRIDE + kk + 4]);
                al[mt][3] = __float_as_uint(Al[(r + 8) * ASTRIDE + kk + 4]);
            }
            #pragma unroll
            for (int nt = 0; nt < 8; ++nt) {
                int n  = wn * 64 + nt * 8 + (lane >> 2);
                int kk = ks + (lane & 3);
                bh[nt][0] = __float_as_uint(Bh[ kk      * BSTRIDE + n]);
                bh[nt][1] = __float_as_uint(Bh[(kk + 4) * BSTRIDE + n]);
                bl[nt][0] = __float_as_uint(Bl[ kk      * BSTRIDE + n]);
                bl[nt][1] = __float_as_uint(Bl[(kk + 4) * BSTRIDE + n]);
            }
            #pragma unroll
            for (int mt = 0; mt < 2; ++mt)
                #pragma unroll
                for (int nt = 0; nt < 8; ++nt) {
                    mma_tf32(c[mt][nt], ah[mt], bh[nt]);
                    mma_tf32(c[mt][nt], al[mt], bh[nt]);
                    mma_tf32(c[mt][nt], ah[mt], bl[nt]);
                }
        }
        __syncthreads();
    }
}

// ------------------------- kernel 1: GEMM + bias + ReLU ---------------------
extern "C" __global__ void __launch_bounds__(256, 1)
k_gemm(const float* __restrict__ A, const float* __restrict__ B,
       const float* __restrict__ bias, float* __restrict__ C,
       int K, int N, int relu)
{
    extern __shared__ float sm[];
    float c[2][8][4] = {};

    const float* Ab = A + (size_t)blockIdx.y * BM * K;
    const float* Bb = B + blockIdx.x * BN;
    gemm_tile(c, Ab, K, Bb, N, K, sm);

    const int lane = threadIdx.x & 31;
    const int wid  = threadIdx.x >> 5;
    const int wm = wid & 3, wn = wid >> 2;
    const int m0 = blockIdx.y * BM, n0 = blockIdx.x * BN;

    #pragma unroll
    for (int mt = 0; mt < 2; ++mt)
        #pragma unroll
        for (int nt = 0; nt < 8; ++nt) {
            int r = m0 + wm * 32 + mt * 16 + (lane >> 2);
            int n = n0 + wn * 64 + nt * 8 + (lane & 3) * 2;
            float b0 = bias[n], b1 = bias[n + 1];
            float v0 = c[mt][nt][0] + b0, v1 = c[mt][nt][1] + b1;
            float v2 = c[mt][nt][2] + b0, v3 = c[mt][nt][3] + b1;
            if (relu) {
                v0 = fmaxf(v0, 0.f); v1 = fmaxf(v1, 0.f);
                v2 = fmaxf(v2, 0.f); v3 = fmaxf(v3, 0.f);
            }
            *reinterpret_cast<float2*>(C + (size_t)r * N + n)       = make_float2(v0, v1);
            *reinterpret_cast<float2*>(C + (size_t)(r + 8) * N + n) = make_float2(v2, v3);
        }
}

// ----------------- kernel 2: rearrange dlt_W3 -> [a][k][f] ------------------
// WdT[a][k][f] = Wd[k][f*32 + a]   (a<32, k<2048, f<512)
extern "C" __global__ void k_transpose_wd(const float* __restrict__ Wd,
                                          float* __restrict__ WdT)
{
    __shared__ float t[32][33];
    const int k   = blockIdx.y;
    const int fg  = blockIdx.x * 32;     // f-group of 32
    const int tid = threadIdx.x;         // 256 threads, 1024 elems

    #pragma unroll
    for (int it = 0; it < 4; ++it) {
        int i = tid + it * 256;          // j = fg*32 + i  ->  f = fg + i/32, a = i%32
        t[i >> 5][i & 31] = Wd[(size_t)k * 16384 + (size_t)fg * 32 + i];
    }
    __syncthreads();
    #pragma unroll
    for (int it = 0; it < 4; ++it) {
        int i  = tid + it * 256;
        int aa = i >> 5, f = i & 31;
        WdT[((size_t)aa * 2048 + k) * 512 + fg + f] = t[f][aa];
    }
}

// ---------- kernel 3: fused last layer (both trunks) + bilinear -------------
// grid: x = f-block (4 of 128), y = action (32), z = batch tile (32 of 128)
extern "C" __global__ void __launch_bounds__(256, 1)
k_fused(const float* __restrict__ Hob, const float* __restrict__ Hdl,
        const float* __restrict__ Wo,  const float* __restrict__ bo,
        const float* __restrict__ WdT, const float* __restrict__ bd,
        float* __restrict__ out)
{
    extern __shared__ float sm[];
    const int fb = blockIdx.x, a = blockIdx.y, bt = blockIdx.z;
    const int K = 2048;

    float cob[2][8][4] = {};
    gemm_tile(cob, Hob + (size_t)bt * BM * K, K,
              Wo + a * 512 + fb * 128, 16384, K, sm);

    float cdl[2][8][4] = {};
    gemm_tile(cdl, Hdl + (size_t)bt * BM * K, K,
              WdT + (size_t)a * K * 512 + fb * 128, 512, K, sm);

    const int lane = threadIdx.x & 31;
    const int wid  = threadIdx.x >> 5;
    const int wm = wid & 3, wn = wid >> 2;

    float psum[2][2] = {};
    #pragma unroll
    for (int mt = 0; mt < 2; ++mt)
        #pragma unroll
        for (int nt = 0; nt < 8; ++nt) {
            int nl = wn * 64 + nt * 8 + (lane & 3) * 2;   // local col 0..127
            int f0 = fb * 128 + nl, f1 = f0 + 1;
            float bo0 = bo[a * 512 + f0], bo1 = bo[a * 512 + f1];
            float bd0 = bd[f0 * 32 + a],  bd1 = bd[f1 * 32 + a];
            float o0 = cob[mt][nt][0] + bo0, o1 = cob[mt][nt][1] + bo1;
            float o2 = cob[mt][nt][2] + bo0, o3 = cob[mt][nt][3] + bo1;
            float d0 = cdl[mt][nt][0] + bd0, d1 = cdl[mt][nt][1] + bd1;
            float d2 = cdl[mt][nt][2] + bd0, d3 = cdl[mt][nt][3] + bd1;
            psum[mt][0] += o0 * d0 + o1 * d1;   // rows r
            psum[mt][1] += o2 * d2 + o3 * d3;   // rows r+8
        }

    #pragma unroll
    for (int mt = 0; mt < 2; ++mt)
        #pragma unroll
        for (int h = 0; h < 2; ++h) {
            float v = psum[mt][h];
            v += __shfl_xor_sync(0xffffffffu, v, 1);
            v += __shfl_xor_sync(0xffffffffu, v, 2);
            if ((lane & 3) == 0) {
                int r = bt * BM + wm * 32 + mt * 16 + h * 8 + (lane >> 2);
                atomicAdd(out + (size_t)r * 32 + a, v);
            }
        }
}

// ------------------------------- launcher -----------------------------------
extern "C" void kernel_launch(void* const* d_in, const int* in_sizes, int n_in,
                              void* d_out, int out_size)
{
    (void)in_sizes; (void)n_in;
    // Input order (setup_inputs dict order):
    //   0: obs, 1: deltas, then per layer i: obs_Wi, obs_bi, dlt_Wi, dlt_bi
    const float* obs = (const float*)d_in[0];
    const float* dlt = (const float*)d_in[1];
    const float *oW[4], *oB[4], *dW[4], *dB[4];
    for (int i = 0; i < 4; ++i) {
        oW[i] = (const float*)d_in[2 + 4 * i];
        oB[i] = (const float*)d_in[3 + 4 * i];
        dW[i] = (const float*)d_in[4 + 4 * i];
        dB[i] = (const float*)d_in[5 + 4 * i];
    }

    float *t0, *t1, *hob, *hdl, *wdt;
    cudaGetSymbolAddress((void**)&t0,  g_t0);
    cudaGetSymbolAddress((void**)&t1,  g_t1);
    cudaGetSymbolAddress((void**)&hob, g_hob);
    cudaGetSymbolAddress((void**)&hdl, g_hdl);
    cudaGetSymbolAddress((void**)&wdt, g_WdT);

    const size_t smem = SMEM_FLOATS * sizeof(float);
    cudaFuncSetAttribute(k_gemm,  cudaFuncAttributeMaxDynamicSharedMemorySize, (int)smem);
    cudaFuncSetAttribute(k_fused, cudaFuncAttributeMaxDynamicSharedMemorySize, (int)smem);

    cudaMemsetAsync(d_out, 0, (size_t)out_size * sizeof(float));

    // Rearrange dlt_W3 so the strided (f*32+a) columns become coalesced.
    k_transpose_wd<<<dim3(16, 2048), 256>>>(dW[3], wdt);

    // obs trunk, layers 0-2 (GEMM + bias + ReLU)
    k_gemm<<<dim3(16, 32), 256, smem>>>(obs, oW[0], oB[0], t0,  256,  2048, 1);
    k_gemm<<<dim3(16, 32), 256, smem>>>(t0,  oW[1], oB[1], t1,  2048, 2048, 1);
    k_gemm<<<dim3(16, 32), 256, smem>>>(t1,  oW[2], oB[2], hob, 2048, 2048, 1);

    // dlt trunk, layers 0-2
    k_gemm<<<dim3(16, 32), 256, smem>>>(dlt, dW[0], dB[0], t0,  256,  2048, 1);
    k_gemm<<<dim3(16, 32), 256, smem>>>(t0,  dW[1], dB[1], t1,  2048, 2048, 1);
    k_gemm<<<dim3(16, 32), 256, smem>>>(t1,  dW[2], dB[2], hdl, 2048, 2048, 1);

    // Fused last layer + bilinear reduction (never materializes [4096,16384]).
    k_fused<<<dim3(4, 32, 32), 256, smem>>>(hob, hdl, oW[3], oB[3], wdt, dB[3],
                                            (float*)d_out);
}

// round 5
// speedup vs baseline: 1.2018x; 1.2018x over previous
#include <cuda_runtime.h>
#include <cstdint>

// ----------------------------------------------------------------------------
// BilinearPolicy: two 4-layer MLP trunks + per-action bilinear contraction.
//   obs:   [4096,256] -> 2048 -> 2048 -> 2048 -> 16384   (ReLU on first 3)
//   dlt:   same shapes, separate weights
//   pred[b,a] = sum_f ob[b, a*512+f] * dl[b, f*32+a]
//
// Round 4: (a) wave-aware grid order in the fused last layer so weights are
// read from DRAM ~once (was 32x), (b) cp.async double-buffered smem pipeline
// with raw-fp32 staging + in-register split-tf32 (3xTF32) for ~fp32 accuracy,
// (c) obs+dlt trunks merged per layer (blockIdx.z) for fewer launches and
// better wave packing.
// ----------------------------------------------------------------------------

#define BM 128
#define BN 128
#define BK 32
#define ASTRIDE 36    // smem row stride (floats) for A tiles  [BM][ASTRIDE]
#define BSTRIDE 136   // smem row stride (floats) for B tiles  [BK][BSTRIDE]
#define BUF_FLOATS (BM * ASTRIDE + BK * BSTRIDE)        // 8960 floats per stage
#define SMEM_FLOATS (2 * BUF_FLOATS)                    // 17920 floats = 71680 B

// ------------------------- static device scratch ----------------------------
__device__ float g_t0 [2ull * 4096 * 2048];     // per-trunk ping  [trunk][B][H]
__device__ float g_t1 [2ull * 4096 * 2048];     // per-trunk pong
__device__ float g_WdT[2048ull * 16384ull];     // dlt_W3 rearranged [a][k][f]

// ------------------------------ helpers -------------------------------------
__device__ __forceinline__ void split2(float v, uint32_t& hi, uint32_t& lo) {
    uint32_t h;
    asm("cvt.rna.tf32.f32 %0, %1;" : "=r"(h) : "f"(v));
    float hf = __uint_as_float(h);
    hi = h;
    lo = __float_as_uint(v - hf);   // exact residual of the tf32 rounding
}

__device__ __forceinline__ void mma_tf32(float* c, const uint32_t* a, const uint32_t* b) {
    asm volatile(
        "mma.sync.aligned.m16n8k8.row.col.f32.tf32.tf32.f32 "
        "{%0,%1,%2,%3},{%4,%5,%6,%7},{%8,%9},{%0,%1,%2,%3};"
        : "+f"(c[0]), "+f"(c[1]), "+f"(c[2]), "+f"(c[3])
        : "r"(a[0]), "r"(a[1]), "r"(a[2]), "r"(a[3]), "r"(b[0]), "r"(b[1]));
}

__device__ __forceinline__ void cp_async16(float* dst, const float* src) {
    uint32_t s = (uint32_t)__cvta_generic_to_shared(dst);
    asm volatile("cp.async.cg.shared.global [%0], [%1], 16;\n" :: "r"(s), "l"(src));
}
#define CP_COMMIT() asm volatile("cp.async.commit_group;\n" ::)
#define CP_WAIT(n)  asm volatile("cp.async.wait_group %0;\n" :: "n"(n))

// Issue async copies for one [BM][BK] A tile and one [BK][BN] B tile.
__device__ __forceinline__ void load_tiles(
    const float* __restrict__ A, int lda,
    const float* __restrict__ B, int ldb,
    int kt, float* As, float* Bs, int tid)
{
    #pragma unroll
    for (int it = 0; it < 4; ++it) {
        int r  = (tid >> 3) + it * 32;
        int kc = (tid & 7) * 4;
        cp_async16(As + r * ASTRIDE + kc, A + (size_t)r * lda + kt + kc);
    }
    #pragma unroll
    for (int it = 0; it < 4; ++it) {
        int idx = tid + it * 256;
        int r   = idx >> 5;
        int nc  = (idx & 31) * 4;
        cp_async16(Bs + r * BSTRIDE + nc, B + (size_t)(kt + r) * ldb + nc);
    }
}

// [BM x BN] tile of A(row-major,lda) @ B(row-major,ldb) over K, split-tf32
// (hi*hi + lo*hi + hi*lo), cp.async double-buffered.
__device__ __forceinline__ void gemm_tile(
    float c[2][8][4],
    const float* __restrict__ A, int lda,
    const float* __restrict__ B, int ldb,
    int K, float* sm)
{
    const int tid  = threadIdx.x;
    const int lane = tid & 31;
    const int wid  = tid >> 5;
    const int wm   = wid & 3;      // 4 warps along M (32 rows each)
    const int wn   = wid >> 2;     // 2 warps along N (64 cols each)
    const int nk   = K / BK;

    load_tiles(A, lda, B, ldb, 0, sm, sm + BM * ASTRIDE, tid);
    CP_COMMIT();

    for (int kt = 0; kt < nk; ++kt) {
        const int cur = kt & 1;
        float* At = sm + cur * BUF_FLOATS;
        float* Bt = At + BM * ASTRIDE;

        if (kt + 1 < nk) {
            float* An = sm + (cur ^ 1) * BUF_FLOATS;
            load_tiles(A, lda, B, ldb, (kt + 1) * BK, An, An + BM * ASTRIDE, tid);
            CP_COMMIT();
            CP_WAIT(1);            // tile kt complete; prefetch may stay in flight
        } else {
            CP_WAIT(0);
        }
        __syncthreads();

        #pragma unroll
        for (int ks = 0; ks < BK; ks += 8) {
            uint32_t ah[2][4], al[2][4], bh[8][2], bl[8][2];
            #pragma unroll
            for (int mt = 0; mt < 2; ++mt) {
                int r  = wm * 32 + mt * 16 + (lane >> 2);
                int kk = ks + (lane & 3);
                split2(At[ r      * ASTRIDE + kk    ], ah[mt][0], al[mt][0]);
                split2(At[(r + 8) * ASTRIDE + kk    ], ah[mt][1], al[mt][1]);
                split2(At[ r      * ASTRIDE + kk + 4], ah[mt][2], al[mt][2]);
                split2(At[(r + 8) * ASTRIDE + kk + 4], ah[mt][3], al[mt][3]);
            }
            #pragma unroll
            for (int nt = 0; nt < 8; ++nt) {
                int n  = wn * 64 + nt * 8 + (lane >> 2);
                int kk = ks + (lane & 3);
                split2(Bt[ kk      * BSTRIDE + n], bh[nt][0], bl[nt][0]);
                split2(Bt[(kk + 4) * BSTRIDE + n], bh[nt][1], bl[nt][1]);
            }
            #pragma unroll
            for (int mt = 0; mt < 2; ++mt)
                #pragma unroll
                for (int nt = 0; nt < 8; ++nt) {
                    mma_tf32(c[mt][nt], ah[mt], bh[nt]);
                    mma_tf32(c[mt][nt], al[mt], bh[nt]);
                    mma_tf32(c[mt][nt], ah[mt], bl[nt]);
                }
        }
        __syncthreads();           // all reads of buffer `cur` done before the
    }                              // kt+2 prefetch overwrites it
}

// ------------- kernel 1: dual-trunk GEMM + bias + ReLU ----------------------
// grid: x = n-tile (16), y = batch-tile (32), z = trunk (0 = obs, 1 = dlt)
extern "C" __global__ void __launch_bounds__(256, 1)
k_gemm2(const float* __restrict__ A0, const float* __restrict__ A1,
        const float* __restrict__ W0, const float* __restrict__ W1,
        const float* __restrict__ b0, const float* __restrict__ b1,
        float* __restrict__ C0, float* __restrict__ C1,
        int K, int N, int relu)
{
    extern __shared__ float sm[];
    const int z = blockIdx.z;
    const float* A    = z ? A1 : A0;
    const float* B    = z ? W1 : W0;
    const float* bias = z ? b1 : b0;
    float*       C    = z ? C1 : C0;

    float c[2][8][4] = {};
    gemm_tile(c, A + (size_t)blockIdx.y * BM * K, K,
              B + blockIdx.x * BN, N, K, sm);

    const int lane = threadIdx.x & 31;
    const int wid  = threadIdx.x >> 5;
    const int wm = wid & 3, wn = wid >> 2;
    const int m0 = blockIdx.y * BM, n0 = blockIdx.x * BN;

    #pragma unroll
    for (int mt = 0; mt < 2; ++mt)
        #pragma unroll
        for (int nt = 0; nt < 8; ++nt) {
            int r = m0 + wm * 32 + mt * 16 + (lane >> 2);
            int n = n0 + wn * 64 + nt * 8 + (lane & 3) * 2;
            float bb0 = bias[n], bb1 = bias[n + 1];
            float v0 = c[mt][nt][0] + bb0, v1 = c[mt][nt][1] + bb1;
            float v2 = c[mt][nt][2] + bb0, v3 = c[mt][nt][3] + bb1;
            if (relu) {
                v0 = fmaxf(v0, 0.f); v1 = fmaxf(v1, 0.f);
                v2 = fmaxf(v2, 0.f); v3 = fmaxf(v3, 0.f);
            }
            *reinterpret_cast<float2*>(C + (size_t)r * N + n)       = make_float2(v0, v1);
            *reinterpret_cast<float2*>(C + (size_t)(r + 8) * N + n) = make_float2(v2, v3);
        }
}

// ----------------- kernel 2: rearrange dlt_W3 -> [a][k][f] ------------------
// WdT[a][k][f] = Wd[k][f*32 + a]   (a<32, k<2048, f<512)
extern "C" __global__ void k_transpose_wd(const float* __restrict__ Wd,
                                          float* __restrict__ WdT)
{
    __shared__ float t[32][33];
    const int k   = blockIdx.y;
    const int fg  = blockIdx.x * 32;     // f-group of 32
    const int tid = threadIdx.x;         // 256 threads, 1024 elems

    #pragma unroll
    for (int it = 0; it < 4; ++it) {
        int i = tid + it * 256;          // f = fg + i/32, a = i%32
        t[i >> 5][i & 31] = Wd[(size_t)k * 16384 + (size_t)fg * 32 + i];
    }
    __syncthreads();
    #pragma unroll
    for (int it = 0; it < 4; ++it) {
        int i  = tid + it * 256;
        int aa = i >> 5, f = i & 31;
        WdT[((size_t)aa * 2048 + k) * 512 + fg + f] = t[f][aa];
    }
}

// ---------- kernel 3: fused last layer (both trunks) + bilinear -------------
// grid: x = batch tile (32, FASTEST -> weight slice reused by a full wave),
//       y = f-block (4 of 128), z = action (32)
extern "C" __global__ void __launch_bounds__(256, 1)
k_fused(const float* __restrict__ Hob, const float* __restrict__ Hdl,
        const float* __restrict__ Wo,  const float* __restrict__ bo,
        const float* __restrict__ WdT, const float* __restrict__ bd,
        float* __restrict__ out)
{
    extern __shared__ float sm[];
    const int bt = blockIdx.x, fb = blockIdx.y, a = blockIdx.z;
    const int K = 2048;

    float cob[2][8][4] = {};
    gemm_tile(cob, Hob + (size_t)bt * BM * K, K,
              Wo + a * 512 + fb * 128, 16384, K, sm);

    float cdl[2][8][4] = {};
    gemm_tile(cdl, Hdl + (size_t)bt * BM * K, K,
              WdT + (size_t)a * K * 512 + fb * 128, 512, K, sm);

    const int lane = threadIdx.x & 31;
    const int wid  = threadIdx.x >> 5;
    const int wm = wid & 3, wn = wid >> 2;

    float psum[2][2] = {};
    #pragma unroll
    for (int mt = 0; mt < 2; ++mt)
        #pragma unroll
        for (int nt = 0; nt < 8; ++nt) {
            int nl = wn * 64 + nt * 8 + (lane & 3) * 2;   // local col 0..127
            int f0 = fb * 128 + nl, f1 = f0 + 1;
            float bo0 = bo[a * 512 + f0], bo1 = bo[a * 512 + f1];
            float bd0 = bd[f0 * 32 + a],  bd1 = bd[f1 * 32 + a];
            float o0 = cob[mt][nt][0] + bo0, o1 = cob[mt][nt][1] + bo1;
            float o2 = cob[mt][nt][2] + bo0, o3 = cob[mt][nt][3] + bo1;
            float d0 = cdl[mt][nt][0] + bd0, d1 = cdl[mt][nt][1] + bd1;
            float d2 = cdl[mt][nt][2] + bd0, d3 = cdl[mt][nt][3] + bd1;
            psum[mt][0] += o0 * d0 + o1 * d1;   // rows r
            psum[mt][1] += o2 * d2 + o3 * d3;   // rows r+8
        }

    #pragma unroll
    for (int mt = 0; mt < 2; ++mt)
        #pragma unroll
        for (int h = 0; h < 2; ++h) {
            float v = psum[mt][h];
            v += __shfl_xor_sync(0xffffffffu, v, 1);
            v += __shfl_xor_sync(0xffffffffu, v, 2);
            if ((lane & 3) == 0) {
                int r = bt * BM + wm * 32 + mt * 16 + h * 8 + (lane >> 2);
                atomicAdd(out + (size_t)r * 32 + a, v);
            }
        }
}

// ------------------------------- launcher -----------------------------------
extern "C" void kernel_launch(void* const* d_in, const int* in_sizes, int n_in,
                              void* d_out, int out_size)
{
    (void)in_sizes; (void)n_in;
    // Input order: 0: obs, 1: deltas, then per layer i: obs_Wi, obs_bi, dlt_Wi, dlt_bi
    const float* obs = (const float*)d_in[0];
    const float* dlt = (const float*)d_in[1];
    const float *oW[4], *oB[4], *dW[4], *dB[4];
    for (int i = 0; i < 4; ++i) {
        oW[i] = (const float*)d_in[2 + 4 * i];
        oB[i] = (const float*)d_in[3 + 4 * i];
        dW[i] = (const float*)d_in[4 + 4 * i];
        dB[i] = (const float*)d_in[5 + 4 * i];
    }

    float *t0, *t1, *wdt;
    cudaGetSymbolAddress((void**)&t0,  g_t0);
    cudaGetSymbolAddress((void**)&t1,  g_t1);
    cudaGetSymbolAddress((void**)&wdt, g_WdT);
    const size_t TRUNK = 4096ull * 2048;   // per-trunk activation slab

    const size_t smem = SMEM_FLOATS * sizeof(float);
    cudaFuncSetAttribute(k_gemm2, cudaFuncAttributeMaxDynamicSharedMemorySize, (int)smem);
    cudaFuncSetAttribute(k_fused, cudaFuncAttributeMaxDynamicSharedMemorySize, (int)smem);

    cudaMemsetAsync(d_out, 0, (size_t)out_size * sizeof(float));

    // Rearrange dlt_W3 so the strided (f*32+a) columns become coalesced.
    k_transpose_wd<<<dim3(16, 2048), 256>>>(dW[3], wdt);

    // Layers 0-2, both trunks per launch (z = trunk).
    k_gemm2<<<dim3(16, 32, 2), 256, smem>>>(obs, dlt, oW[0], dW[0], oB[0], dB[0],
                                            t0, t0 + TRUNK, 256, 2048, 1);
    k_gemm2<<<dim3(16, 32, 2), 256, smem>>>(t0, t0 + TRUNK, oW[1], dW[1], oB[1], dB[1],
                                            t1, t1 + TRUNK, 2048, 2048, 1);
    k_gemm2<<<dim3(16, 32, 2), 256, smem>>>(t1, t1 + TRUNK, oW[2], dW[2], oB[2], dB[2],
                                            t0, t0 + TRUNK, 2048, 2048, 1);

    // Fused last layer + bilinear reduction (never materializes [4096,16384]).
    // bt fastest: a 148-CTA wave shares ~4.6 weight slices via L2.
    k_fused<<<dim3(32, 4, 32), 256, smem>>>(t0, t0 + TRUNK, oW[3], oB[3], wdt, dB[3],
                                            (float*)d_out);
}

// round 7
// speedup vs baseline: 1.7497x; 1.4559x over previous
#include <cuda_runtime.h>
#include <cstdint>

// ----------------------------------------------------------------------------
// BilinearPolicy: two 4-layer MLP trunks + per-action bilinear contraction.
//   obs:   [4096,256] -> 2048 -> 2048 -> 2048 -> 16384   (ReLU on first 3)
//   dlt:   same shapes, separate weights
//   pred[b,a] = sum_f ob[b, a*512+f] * dl[b, f*32+a]
//
// Round 6 (= round 5 resubmit; infra never ran it): tensor-bound per ncu
// (tensor 67%, DRAM 1.5%). Split-3 GEMM core uses 3xBF16 m16n8k16 instead of
// 3xTF32 m16n8k8 -> half the tensor instructions at ~fp32 accuracy.
// Keeps: wave-aware fused grid (weights read ~once), cp.async double buffer,
// merged dual-trunk layer launches.
// ----------------------------------------------------------------------------

#define BM 128
#define BN 128
#define BK 32
#define ASTRIDE 36    // smem row stride (floats) for A tiles  [BM][ASTRIDE]
#define BSTRIDE 132   // smem row stride (floats) for B tiles  [BK][BSTRIDE]
                      //   132: paired-k fragment loads hit distinct banks
#define BUF_FLOATS (BM * ASTRIDE + BK * BSTRIDE)        // 8832 floats per stage
#define SMEM_FLOATS (2 * BUF_FLOATS)                    // 17664 floats = 70656 B

// ------------------------- static device scratch ----------------------------
__device__ float g_t0 [2ull * 4096 * 2048];     // per-trunk ping  [trunk][B][H]
__device__ float g_t1 [2ull * 4096 * 2048];     // per-trunk pong
__device__ float g_WdT[2048ull * 16384ull];     // dlt_W3 rearranged [a][k][f]

// ------------------------------ helpers -------------------------------------
// Split two adjacent-k fp32 values into packed bf16x2 hi and lo parts.
// hi = {bf16(v1) : bf16(v0)}, lo = {bf16(v1-hi1) : bf16(v0-hi0)}  (lo = low k)
__device__ __forceinline__ void split_bf2(float v0, float v1,
                                          uint32_t& hi, uint32_t& lo) {
    uint32_t h;
    asm("cvt.rn.bf16x2.f32 %0, %1, %2;" : "=r"(h) : "f"(v1), "f"(v0));
    float f0 = __uint_as_float(h << 16);
    float f1 = __uint_as_float(h & 0xffff0000u);
    float r0 = v0 - f0;
    float r1 = v1 - f1;
    asm("cvt.rn.bf16x2.f32 %0, %1, %2;" : "=r"(lo) : "f"(r1), "f"(r0));
    hi = h;
}

__device__ __forceinline__ void mma_bf16(float* c, const uint32_t* a, const uint32_t* b) {
    asm volatile(
        "mma.sync.aligned.m16n8k16.row.col.f32.bf16.bf16.f32 "
        "{%0,%1,%2,%3},{%4,%5,%6,%7},{%8,%9},{%0,%1,%2,%3};"
        : "+f"(c[0]), "+f"(c[1]), "+f"(c[2]), "+f"(c[3])
        : "r"(a[0]), "r"(a[1]), "r"(a[2]), "r"(a[3]), "r"(b[0]), "r"(b[1]));
}

__device__ __forceinline__ void cp_async16(float* dst, const float* src) {
    uint32_t s = (uint32_t)__cvta_generic_to_shared(dst);
    asm volatile("cp.async.cg.shared.global [%0], [%1], 16;\n" :: "r"(s), "l"(src));
}
#define CP_COMMIT() asm volatile("cp.async.commit_group;\n" ::)
#define CP_WAIT(n)  asm volatile("cp.async.wait_group %0;\n" :: "n"(n))

// Issue async copies for one [BM][BK] A tile and one [BK][BN] B tile.
__device__ __forceinline__ void load_tiles(
    const float* __restrict__ A, int lda,
    const float* __restrict__ B, int ldb,
    int kt, float* As, float* Bs, int tid)
{
    #pragma unroll
    for (int it = 0; it < 4; ++it) {
        int r  = (tid >> 3) + it * 32;
        int kc = (tid & 7) * 4;
        cp_async16(As + r * ASTRIDE + kc, A + (size_t)r * lda + kt + kc);
    }
    #pragma unroll
    for (int it = 0; it < 4; ++it) {
        int idx = tid + it * 256;
        int r   = idx >> 5;
        int nc  = (idx & 31) * 4;
        cp_async16(Bs + r * BSTRIDE + nc, B + (size_t)(kt + r) * ldb + nc);
    }
}

// [BM x BN] tile of A(row-major,lda) @ B(row-major,ldb) over K.
// bf16 split-3 (hi*hi + lo*hi + hi*lo), cp.async double-buffered.
__device__ __forceinline__ void gemm_tile(
    float c[2][8][4],
    const float* __restrict__ A, int lda,
    const float* __restrict__ B, int ldb,
    int K, float* sm)
{
    const int tid  = threadIdx.x;
    const int lane = tid & 31;
    const int wid  = tid >> 5;
    const int wm   = wid & 3;      // 4 warps along M (32 rows each)
    const int wn   = wid >> 2;     // 2 warps along N (64 cols each)
    const int nk   = K / BK;

    load_tiles(A, lda, B, ldb, 0, sm, sm + BM * ASTRIDE, tid);
    CP_COMMIT();

    for (int kt = 0; kt < nk; ++kt) {
        const int cur = kt & 1;
        float* At = sm + cur * BUF_FLOATS;
        float* Bt = At + BM * ASTRIDE;

        if (kt + 1 < nk) {
            float* An = sm + (cur ^ 1) * BUF_FLOATS;
            load_tiles(A, lda, B, ldb, (kt + 1) * BK, An, An + BM * ASTRIDE, tid);
            CP_COMMIT();
            CP_WAIT(1);            // tile kt complete; prefetch may stay in flight
        } else {
            CP_WAIT(0);
        }
        __syncthreads();

        // 2 k-steps of 16 (m16n8k16 bf16)
        #pragma unroll
        for (int ks = 0; ks < BK; ks += 16) {
            const int k0 = ks + (lane & 3) * 2;
            uint32_t ah[2][4], al[2][4], bh[8][2], bl[8][2];
            #pragma unroll
            for (int mt = 0; mt < 2; ++mt) {
                int r = wm * 32 + mt * 16 + (lane >> 2);
                const float* a0 = At +  r      * ASTRIDE;
                const float* a1 = At + (r + 8) * ASTRIDE;
                split_bf2(a0[k0    ], a0[k0 + 1], ah[mt][0], al[mt][0]);
                split_bf2(a1[k0    ], a1[k0 + 1], ah[mt][1], al[mt][1]);
                split_bf2(a0[k0 + 8], a0[k0 + 9], ah[mt][2], al[mt][2]);
                split_bf2(a1[k0 + 8], a1[k0 + 9], ah[mt][3], al[mt][3]);
            }
            #pragma unroll
            for (int nt = 0; nt < 8; ++nt) {
                int n = wn * 64 + nt * 8 + (lane >> 2);
                split_bf2(Bt[ k0      * BSTRIDE + n], Bt[(k0 + 1) * BSTRIDE + n],
                          bh[nt][0], bl[nt][0]);
                split_bf2(Bt[(k0 + 8) * BSTRIDE + n], Bt[(k0 + 9) * BSTRIDE + n],
                          bh[nt][1], bl[nt][1]);
            }
            #pragma unroll
            for (int mt = 0; mt < 2; ++mt)
                #pragma unroll
                for (int nt = 0; nt < 8; ++nt) {
                    mma_bf16(c[mt][nt], ah[mt], bh[nt]);
                    mma_bf16(c[mt][nt], al[mt], bh[nt]);
                    mma_bf16(c[mt][nt], ah[mt], bl[nt]);
                }
        }
        __syncthreads();           // all reads of buffer `cur` done before the
    }                              // kt+2 prefetch overwrites it
}

// ------------- kernel 1: dual-trunk GEMM + bias + ReLU ----------------------
// grid: x = n-tile (16), y = batch-tile (32), z = trunk (0 = obs, 1 = dlt)
extern "C" __global__ void __launch_bounds__(256, 1)
k_gemm2(const float* __restrict__ A0, const float* __restrict__ A1,
        const float* __restrict__ W0, const float* __restrict__ W1,
        const float* __restrict__ b0, const float* __restrict__ b1,
        float* __restrict__ C0, float* __restrict__ C1,
        int K, int N, int relu)
{
    extern __shared__ float sm[];
    const int z = blockIdx.z;
    const float* A    = z ? A1 : A0;
    const float* B    = z ? W1 : W0;
    const float* bias = z ? b1 : b0;
    float*       C    = z ? C1 : C0;

    float c[2][8][4] = {};
    gemm_tile(c, A + (size_t)blockIdx.y * BM * K, K,
              B + blockIdx.x * BN, N, K, sm);

    const int lane = threadIdx.x & 31;
    const int wid  = threadIdx.x >> 5;
    const int wm = wid & 3, wn = wid >> 2;
    const int m0 = blockIdx.y * BM, n0 = blockIdx.x * BN;

    #pragma unroll
    for (int mt = 0; mt < 2; ++mt)
        #pragma unroll
        for (int nt = 0; nt < 8; ++nt) {
            int r = m0 + wm * 32 + mt * 16 + (lane >> 2);
            int n = n0 + wn * 64 + nt * 8 + (lane & 3) * 2;
            float bb0 = bias[n], bb1 = bias[n + 1];
            float v0 = c[mt][nt][0] + bb0, v1 = c[mt][nt][1] + bb1;
            float v2 = c[mt][nt][2] + bb0, v3 = c[mt][nt][3] + bb1;
            if (relu) {
                v0 = fmaxf(v0, 0.f); v1 = fmaxf(v1, 0.f);
                v2 = fmaxf(v2, 0.f); v3 = fmaxf(v3, 0.f);
            }
            *reinterpret_cast<float2*>(C + (size_t)r * N + n)       = make_float2(v0, v1);
            *reinterpret_cast<float2*>(C + (size_t)(r + 8) * N + n) = make_float2(v2, v3);
        }
}

// ----------------- kernel 2: rearrange dlt_W3 -> [a][k][f] ------------------
// WdT[a][k][f] = Wd[k][f*32 + a]   (a<32, k<2048, f<512)
extern "C" __global__ void k_transpose_wd(const float* __restrict__ Wd,
                                          float* __restrict__ WdT)
{
    __shared__ float t[32][33];
    const int k   = blockIdx.y;
    const int fg  = blockIdx.x * 32;     // f-group of 32
    const int tid = threadIdx.x;         // 256 threads, 1024 elems

    #pragma unroll
    for (int it = 0; it < 4; ++it) {
        int i = tid + it * 256;          // f = fg + i/32, a = i%32
        t[i >> 5][i & 31] = Wd[(size_t)k * 16384 + (size_t)fg * 32 + i];
    }
    __syncthreads();
    #pragma unroll
    for (int it = 0; it < 4; ++it) {
        int i  = tid + it * 256;
        int aa = i >> 5, f = i & 31;
        WdT[((size_t)aa * 2048 + k) * 512 + fg + f] = t[f][aa];
    }
}

// ---------- kernel 3: fused last layer (both trunks) + bilinear -------------
// grid: x = batch tile (32, FASTEST -> weight slice reused by a full wave),
//       y = f-block (4 of 128), z = action (32)
extern "C" __global__ void __launch_bounds__(256, 1)
k_fused(const float* __restrict__ Hob, const float* __restrict__ Hdl,
        const float* __restrict__ Wo,  const float* __restrict__ bo,
        const float* __restrict__ WdT, const float* __restrict__ bd,
        float* __restrict__ out)
{
    extern __shared__ float sm[];
    const int bt = blockIdx.x, fb = blockIdx.y, a = blockIdx.z;
    const int K = 2048;

    float cob[2][8][4] = {};
    gemm_tile(cob, Hob + (size_t)bt * BM * K, K,
              Wo + a * 512 + fb * 128, 16384, K, sm);

    float cdl[2][8][4] = {};
    gemm_tile(cdl, Hdl + (size_t)bt * BM * K, K,
              WdT + (size_t)a * K * 512 + fb * 128, 512, K, sm);

    const int lane = threadIdx.x & 31;
    const int wid  = threadIdx.x >> 5;
    const int wm = wid & 3, wn = wid >> 2;

    float psum[2][2] = {};
    #pragma unroll
    for (int mt = 0; mt < 2; ++mt)
        #pragma unroll
        for (int nt = 0; nt < 8; ++nt) {
            int nl = wn * 64 + nt * 8 + (lane & 3) * 2;   // local col 0..127
            int f0 = fb * 128 + nl, f1 = f0 + 1;
            float bo0 = bo[a * 512 + f0], bo1 = bo[a * 512 + f1];
            float bd0 = bd[f0 * 32 + a],  bd1 = bd[f1 * 32 + a];
            float o0 = cob[mt][nt][0] + bo0, o1 = cob[mt][nt][1] + bo1;
            float o2 = cob[mt][nt][2] + bo0, o3 = cob[mt][nt][3] + bo1;
            float d0 = cdl[mt][nt][0] + bd0, d1 = cdl[mt][nt][1] + bd1;
            float d2 = cdl[mt][nt][2] + bd0, d3 = cdl[mt][nt][3] + bd1;
            psum[mt][0] += o0 * d0 + o1 * d1;   // rows r
            psum[mt][1] += o2 * d2 + o3 * d3;   // rows r+8
        }

    #pragma unroll
    for (int mt = 0; mt < 2; ++mt)
        #pragma unroll
        for (int h = 0; h < 2; ++h) {
            float v = psum[mt][h];
            v += __shfl_xor_sync(0xffffffffu, v, 1);
            v += __shfl_xor_sync(0xffffffffu, v, 2);
            if ((lane & 3) == 0) {
                int r = bt * BM + wm * 32 + mt * 16 + h * 8 + (lane >> 2);
                atomicAdd(out + (size_t)r * 32 + a, v);
            }
        }
}

// ------------------------------- launcher -----------------------------------
extern "C" void kernel_launch(void* const* d_in, const int* in_sizes, int n_in,
                              void* d_out, int out_size)
{
    (void)in_sizes; (void)n_in;
    // Input order: 0: obs, 1: deltas, then per layer i: obs_Wi, obs_bi, dlt_Wi, dlt_bi
    const float* obs = (const float*)d_in[0];
    const float* dlt = (const float*)d_in[1];
    const float *oW[4], *oB[4], *dW[4], *dB[4];
    for (int i = 0; i < 4; ++i) {
        oW[i] = (const float*)d_in[2 + 4 * i];
        oB[i] = (const float*)d_in[3 + 4 * i];
        dW[i] = (const float*)d_in[4 + 4 * i];
        dB[i] = (const float*)d_in[5 + 4 * i];
    }

    float *t0, *t1, *wdt;
    cudaGetSymbolAddress((void**)&t0,  g_t0);
    cudaGetSymbolAddress((void**)&t1,  g_t1);
    cudaGetSymbolAddress((void**)&wdt, g_WdT);
    const size_t TRUNK = 4096ull * 2048;   // per-trunk activation slab

    const size_t smem = SMEM_FLOATS * sizeof(float);
    cudaFuncSetAttribute(k_gemm2, cudaFuncAttributeMaxDynamicSharedMemorySize, (int)smem);
    cudaFuncSetAttribute(k_fused, cudaFuncAttributeMaxDynamicSharedMemorySize, (int)smem);

    cudaMemsetAsync(d_out, 0, (size_t)out_size * sizeof(float));

    // Rearrange dlt_W3 so the strided (f*32+a) columns become coalesced.
    k_transpose_wd<<<dim3(16, 2048), 256>>>(dW[3], wdt);

    // Layers 0-2, both trunks per launch (z = trunk).
    k_gemm2<<<dim3(16, 32, 2), 256, smem>>>(obs, dlt, oW[0], dW[0], oB[0], dB[0],
                                            t0, t0 + TRUNK, 256, 2048, 1);
    k_gemm2<<<dim3(16, 32, 2), 256, smem>>>(t0, t0 + TRUNK, oW[1], dW[1], oB[1], dB[1],
                                            t1, t1 + TRUNK, 2048, 2048, 1);
    k_gemm2<<<dim3(16, 32, 2), 256, smem>>>(t1, t1 + TRUNK, oW[2], dW[2], oB[2], dB[2],
                                            t0, t0 + TRUNK, 2048, 2048, 1);

    // Fused last layer + bilinear reduction (never materializes [4096,16384]).
    // bt fastest: a 148-CTA wave shares ~4.6 weight slices via L2.
    k_fused<<<dim3(32, 4, 32), 256, smem>>>(t0, t0 + TRUNK, oW[3], oB[3], wdt, dB[3],
                                            (float*)d_out);
}

// round 8
// speedup vs baseline: 1.8167x; 1.0383x over previous
#include <cuda_runtime.h>
#include <cstdint>

// ----------------------------------------------------------------------------
// BilinearPolicy: two 4-layer MLP trunks + per-action bilinear contraction.
//   pred[b,a] = sum_f ob[b, a*512+f] * dl[b, f*32+a]
//
// Round 8: inner loop was issue-bound (tensor 47%, occ 12.5%). All bf16
// split-3 work moved OUT of the hot loop: weights pre-split per call into
// packed uint2{hi_bf16x2, lo_bf16x2}; activations written pre-split by the
// GEMM epilogue (same bytes as fp32). Inner loop = LDS.64 + mma only.
// 2 CTAs/SM via __launch_bounds__(256,2). Math identical to round 7.
// ----------------------------------------------------------------------------

#define BM 128
#define BN 128
#define BK 32
#define AST 20    // uint2 per A-tile row (16 data + 4 pad) - conflict-free LDS.64
#define BST 132   // uint2 per B-tile k2-row (128 data + 4 pad) - conflict-free
#define BUF_U2 (BM * AST + (BK / 2) * BST)   // 2560 + 2112 = 4672 uint2
#define SMEM_U2 (2 * BUF_U2)                 // 9344 uint2 = 74752 B

// ------------------------- static device scratch ----------------------------
__device__ uint2 g_inp [2ull * 4096 * 128];     // packed obs / deltas
__device__ uint2 g_a0  [2ull * 4096 * 1024];    // packed activations ping
__device__ uint2 g_a1  [2ull * 4096 * 1024];    // packed activations pong
__device__ uint2 g_w0p [2ull * 128 * 2048];     // packed W0 (both trunks)
__device__ uint2 g_w1p [2ull * 1024 * 2048];    // packed W1
__device__ uint2 g_w2p [2ull * 1024 * 2048];    // packed W2
__device__ uint2 g_w3p [1024ull * 16384];       // packed obs_W3
__device__ uint2 g_wdtp[32ull * 1024 * 512];    // packed transposed dlt_W3 [a][k2][f]

// ------------------------------ helpers -------------------------------------
// Split two adjacent-k fp32 values into packed bf16x2 hi and lo words.
__device__ __forceinline__ void split_bf2(float v0, float v1,
                                          uint32_t& hi, uint32_t& lo) {
    uint32_t h;
    asm("cvt.rn.bf16x2.f32 %0, %1, %2;" : "=r"(h) : "f"(v1), "f"(v0));
    float f0 = __uint_as_float(h << 16);
    float f1 = __uint_as_float(h & 0xffff0000u);
    float r0 = v0 - f0;
    float r1 = v1 - f1;
    asm("cvt.rn.bf16x2.f32 %0, %1, %2;" : "=r"(lo) : "f"(r1), "f"(r0));
    hi = h;
}

__device__ __forceinline__ void mma_bf16(float* c, const uint32_t* a, const uint32_t* b) {
    asm volatile(
        "mma.sync.aligned.m16n8k16.row.col.f32.bf16.bf16.f32 "
        "{%0,%1,%2,%3},{%4,%5,%6,%7},{%8,%9},{%0,%1,%2,%3};"
        : "+f"(c[0]), "+f"(c[1]), "+f"(c[2]), "+f"(c[3])
        : "r"(a[0]), "r"(a[1]), "r"(a[2]), "r"(a[3]), "r"(b[0]), "r"(b[1]));
}

__device__ __forceinline__ void cp_async16(void* dst, const void* src) {
    uint32_t s = (uint32_t)__cvta_generic_to_shared(dst);
    asm volatile("cp.async.cg.shared.global [%0], [%1], 16;\n" :: "r"(s), "l"(src));
}
#define CP_COMMIT() asm volatile("cp.async.commit_group;\n" ::)
#define CP_WAIT(n)  asm volatile("cp.async.wait_group %0;\n" :: "n"(n))

// Issue async copies for one [BM][BK/2] A tile and one [BK/2][BN] B tile
// (all units are uint2 = one packed k-pair).
__device__ __forceinline__ void load_tiles(
    const uint2* __restrict__ A, int lda2,
    const uint2* __restrict__ B, int ldb,
    int kt2, uint2* As, uint2* Bs, int tid)
{
    #pragma unroll
    for (int it = 0; it < 4; ++it) {
        int r  = (tid >> 3) + it * 32;
        int kc = (tid & 7) * 2;
        cp_async16(As + r * AST + kc, A + (size_t)r * lda2 + kt2 + kc);
    }
    #pragma unroll
    for (int it = 0; it < 4; ++it) {
        int idx = tid + it * 256;
        int r   = idx >> 6;             // 0..15
        int nc  = (idx & 63) * 2;
        cp_async16(Bs + r * BST + nc, B + (size_t)(kt2 + r) * ldb + nc);
    }
}

// [BM x BN] tile of A @ B over K; operands pre-split packed bf16 (hi,lo).
// Split-3: hi*hi + lo*hi + hi*lo. cp.async double-buffered.
__device__ __forceinline__ void gemm_tile(
    float c[2][8][4],
    const uint2* __restrict__ A, int lda2,
    const uint2* __restrict__ B, int ldb,
    int K, uint2* sm)
{
    const int tid  = threadIdx.x;
    const int lane = tid & 31;
    const int wid  = tid >> 5;
    const int wm   = wid & 3;      // 4 warps along M
    const int wn   = wid >> 2;     // 2 warps along N
    const int nk   = K / BK;

    load_tiles(A, lda2, B, ldb, 0, sm, sm + BM * AST, tid);
    CP_COMMIT();

    for (int kt = 0; kt < nk; ++kt) {
        const int cur = kt & 1;
        uint2* At = sm + cur * BUF_U2;
        uint2* Bt = At + BM * AST;

        if (kt + 1 < nk) {
            uint2* An = sm + (cur ^ 1) * BUF_U2;
            load_tiles(A, lda2, B, ldb, (kt + 1) * (BK / 2), An, An + BM * AST, tid);
            CP_COMMIT();
            CP_WAIT(1);            // tile kt resident; prefetch may stay in flight
        } else {
            CP_WAIT(0);
        }
        __syncthreads();

        #pragma unroll
        for (int ks = 0; ks < 2; ++ks) {           // two k16 steps per k-tile
            const int k2 = ks * 8 + (lane & 3);
            uint32_t ah[2][4], al[2][4];
            #pragma unroll
            for (int mt = 0; mt < 2; ++mt) {
                int r = wm * 32 + mt * 16 + (lane >> 2);
                uint2 w;
                w = At[ r      * AST + k2    ]; ah[mt][0] = w.x; al[mt][0] = w.y;
                w = At[(r + 8) * AST + k2    ]; ah[mt][1] = w.x; al[mt][1] = w.y;
                w = At[ r      * AST + k2 + 4]; ah[mt][2] = w.x; al[mt][2] = w.y;
                w = At[(r + 8) * AST + k2 + 4]; ah[mt][3] = w.x; al[mt][3] = w.y;
            }
            #pragma unroll
            for (int ng = 0; ng < 2; ++ng) {       // B fragments in 2 groups of 4
                uint32_t bh[4][2], bl[4][2];
                #pragma unroll
                for (int nt = 0; nt < 4; ++nt) {
                    int n = wn * 64 + (ng * 4 + nt) * 8 + (lane >> 2);
                    uint2 w;
                    w = Bt[ k2      * BST + n]; bh[nt][0] = w.x; bl[nt][0] = w.y;
                    w = Bt[(k2 + 4) * BST + n]; bh[nt][1] = w.x; bl[nt][1] = w.y;
                }
                #pragma unroll
                for (int mt = 0; mt < 2; ++mt)
                    #pragma unroll
                    for (int nt = 0; nt < 4; ++nt) {
                        float* cc = c[mt][ng * 4 + nt];
                        mma_bf16(cc, ah[mt], bh[nt]);
                        mma_bf16(cc, al[mt], bh[nt]);
                        mma_bf16(cc, ah[mt], bl[nt]);
                    }
            }
        }
        __syncthreads();           // reads of buffer `cur` done before kt+2 prefetch
    }
}

// -------------------- packing preamble kernels ------------------------------
// Pack activations/inputs: pairs adjacent columns of fp32 [rows][C].
extern "C" __global__ void k_pack_act(const float* __restrict__ x0,
                                      const float* __restrict__ x1,
                                      uint2* __restrict__ y0,
                                      uint2* __restrict__ y1, int n2)
{
    int i = blockIdx.x * blockDim.x + threadIdx.x;
    if (i >= n2) return;
    const float* x = blockIdx.y ? x1 : x0;
    uint2*       y = blockIdx.y ? y1 : y0;
    float2 v = reinterpret_cast<const float2*>(x)[i];
    uint2 p; split_bf2(v.x, v.y, p.x, p.y);
    y[i] = p;
}

// Pack weights: pairs adjacent K-rows of fp32 W[K][N] -> Wp[K/2][N].
extern "C" __global__ void k_pack_w(const float* __restrict__ w0,
                                    const float* __restrict__ w1,
                                    uint2* __restrict__ y0,
                                    uint2* __restrict__ y1,
                                    int N, int total)   // total = (K/2)*N
{
    int i = blockIdx.x * blockDim.x + threadIdx.x;
    if (i >= total) return;
    const float* w = blockIdx.y ? w1 : w0;
    uint2*       y = blockIdx.y ? y1 : y0;
    int k2 = i / N, n = i - k2 * N;
    float a = w[(size_t)(2 * k2)     * N + n];
    float b = w[(size_t)(2 * k2 + 1) * N + n];
    uint2 p; split_bf2(a, b, p.x, p.y);
    y[i] = p;
}

// Transpose + pack dlt_W3: WdTp[a][k2][f] = pack(Wd[2k2][f*32+a], Wd[2k2+1][f*32+a])
extern "C" __global__ void k_transpose_wd(const float* __restrict__ Wd,
                                          uint2* __restrict__ WdTp)
{
    __shared__ float t0[32][33], t1[32][33];
    const int k2  = blockIdx.y;          // 0..1023
    const int fg  = blockIdx.x * 32;     // f-group of 32
    const int tid = threadIdx.x;         // 256 threads, 1024 elems per row

    const size_t r0 = (size_t)(2 * k2) * 16384 + (size_t)fg * 32;
    const size_t r1 = r0 + 16384;
    #pragma unroll
    for (int it = 0; it < 4; ++it) {
        int i = tid + it * 256;          // i = f_local*32 + a
        t0[i >> 5][i & 31] = Wd[r0 + i];
        t1[i >> 5][i & 31] = Wd[r1 + i];
    }
    __syncthreads();
    #pragma unroll
    for (int it = 0; it < 4; ++it) {
        int i = tid + it * 256;
        int a = i >> 5, f = i & 31;
        uint2 p; split_bf2(t0[f][a], t1[f][a], p.x, p.y);
        WdTp[((size_t)a * 1024 + k2) * 512 + fg + f] = p;
    }
}

// ------------- kernel: dual-trunk GEMM + bias + ReLU, packed I/O ------------
// grid: x = n-tile (16), y = batch-tile (32), z = trunk (0 = obs, 1 = dlt)
extern "C" __global__ void __launch_bounds__(256, 2)
k_gemm2(const uint2* __restrict__ A0, const uint2* __restrict__ A1,
        const uint2* __restrict__ W0, const uint2* __restrict__ W1,
        const float* __restrict__ b0, const float* __restrict__ b1,
        uint2* __restrict__ C0, uint2* __restrict__ C1,
        int K, int N, int relu)
{
    extern __shared__ uint2 sm[];
    const int z = blockIdx.z;
    const uint2* A    = z ? A1 : A0;
    const uint2* B    = z ? W1 : W0;
    const float* bias = z ? b1 : b0;
    uint2*       C    = z ? C1 : C0;

    float c[2][8][4] = {};
    gemm_tile(c, A + (size_t)blockIdx.y * BM * (K / 2), K / 2,
              B + blockIdx.x * BN, N, K, sm);

    const int lane = threadIdx.x & 31;
    const int wid  = threadIdx.x >> 5;
    const int wm = wid & 3, wn = wid >> 2;
    const int m0 = blockIdx.y * BM, n0 = blockIdx.x * BN;
    const int N2 = N >> 1;

    #pragma unroll
    for (int mt = 0; mt < 2; ++mt)
        #pragma unroll
        for (int nt = 0; nt < 8; ++nt) {
            int r = m0 + wm * 32 + mt * 16 + (lane >> 2);
            int n = n0 + wn * 64 + nt * 8 + (lane & 3) * 2;
            float bb0 = bias[n], bb1 = bias[n + 1];
            float v0 = c[mt][nt][0] + bb0, v1 = c[mt][nt][1] + bb1;
            float v2 = c[mt][nt][2] + bb0, v3 = c[mt][nt][3] + bb1;
            if (relu) {
                v0 = fmaxf(v0, 0.f); v1 = fmaxf(v1, 0.f);
                v2 = fmaxf(v2, 0.f); v3 = fmaxf(v3, 0.f);
            }
            uint2 p0; split_bf2(v0, v1, p0.x, p0.y);
            uint2 p1; split_bf2(v2, v3, p1.x, p1.y);
            C[(size_t)r * N2 + (n >> 1)]       = p0;
            C[(size_t)(r + 8) * N2 + (n >> 1)] = p1;
        }
}

// ---------- kernel: fused last layer (both trunks) + bilinear ---------------
// grid: x = batch tile (32, FASTEST -> weight slice reused by a full wave),
//       y = f-block (4 of 128), z = action (32)
extern "C" __global__ void __launch_bounds__(256, 2)
k_fused(const uint2* __restrict__ Hob, const uint2* __restrict__ Hdl,
        const uint2* __restrict__ Wo,  const float* __restrict__ bo,
        const uint2* __restrict__ WdTp, const float* __restrict__ bd,
        float* __restrict__ out)
{
    extern __shared__ uint2 sm[];
    const int bt = blockIdx.x, fb = blockIdx.y, a = blockIdx.z;

    float cob[2][8][4] = {};
    gemm_tile(cob, Hob + (size_t)bt * BM * 1024, 1024,
              Wo + a * 512 + fb * 128, 16384, 2048, sm);

    float cdl[2][8][4] = {};
    gemm_tile(cdl, Hdl + (size_t)bt * BM * 1024, 1024,
              WdTp + (size_t)a * 1024 * 512 + fb * 128, 512, 2048, sm);

    const int lane = threadIdx.x & 31;
    const int wid  = threadIdx.x >> 5;
    const int wm = wid & 3, wn = wid >> 2;

    float psum[2][2] = {};
    #pragma unroll
    for (int mt = 0; mt < 2; ++mt)
        #pragma unroll
        for (int nt = 0; nt < 8; ++nt) {
            int nl = wn * 64 + nt * 8 + (lane & 3) * 2;   // local col 0..127
            int f0 = fb * 128 + nl, f1 = f0 + 1;
            float bo0 = bo[a * 512 + f0], bo1 = bo[a * 512 + f1];
            float bd0 = bd[f0 * 32 + a],  bd1 = bd[f1 * 32 + a];
            float o0 = cob[mt][nt][0] + bo0, o1 = cob[mt][nt][1] + bo1;
            float o2 = cob[mt][nt][2] + bo0, o3 = cob[mt][nt][3] + bo1;
            float d0 = cdl[mt][nt][0] + bd0, d1 = cdl[mt][nt][1] + bd1;
            float d2 = cdl[mt][nt][2] + bd0, d3 = cdl[mt][nt][3] + bd1;
            psum[mt][0] += o0 * d0 + o1 * d1;   // rows r
            psum[mt][1] += o2 * d2 + o3 * d3;   // rows r+8
        }

    #pragma unroll
    for (int mt = 0; mt < 2; ++mt)
        #pragma unroll
        for (int h = 0; h < 2; ++h) {
            float v = psum[mt][h];
            v += __shfl_xor_sync(0xffffffffu, v, 1);
            v += __shfl_xor_sync(0xffffffffu, v, 2);
            if ((lane & 3) == 0) {
                int r = bt * BM + wm * 32 + mt * 16 + h * 8 + (lane >> 2);
                atomicAdd(out + (size_t)r * 32 + a, v);
            }
        }
}

// ------------------------------- launcher -----------------------------------
extern "C" void kernel_launch(void* const* d_in, const int* in_sizes, int n_in,
                              void* d_out, int out_size)
{
    (void)in_sizes; (void)n_in;
    // Input order: 0: obs, 1: deltas, then per layer i: obs_Wi, obs_bi, dlt_Wi, dlt_bi
    const float* obs = (const float*)d_in[0];
    const float* dlt = (const float*)d_in[1];
    const float *oW[4], *oB[4], *dW[4], *dB[4];
    for (int i = 0; i < 4; ++i) {
        oW[i] = (const float*)d_in[2 + 4 * i];
        oB[i] = (const float*)d_in[3 + 4 * i];
        dW[i] = (const float*)d_in[4 + 4 * i];
        dB[i] = (const float*)d_in[5 + 4 * i];
    }

    uint2 *inp, *a0, *a1, *w0p, *w1p, *w2p, *w3p, *wdtp;
    cudaGetSymbolAddress((void**)&inp,  g_inp);
    cudaGetSymbolAddress((void**)&a0,   g_a0);
    cudaGetSymbolAddress((void**)&a1,   g_a1);
    cudaGetSymbolAddress((void**)&w0p,  g_w0p);
    cudaGetSymbolAddress((void**)&w1p,  g_w1p);
    cudaGetSymbolAddress((void**)&w2p,  g_w2p);
    cudaGetSymbolAddress((void**)&w3p,  g_w3p);
    cudaGetSymbolAddress((void**)&wdtp, g_wdtp);

    const size_t IN   = 4096ull * 128;    // packed input slab per trunk
    const size_t ACT  = 4096ull * 1024;   // packed activation slab per trunk
    const size_t W0S  = 128ull * 2048;
    const size_t W12S = 1024ull * 2048;

    const size_t smem = SMEM_U2 * sizeof(uint2);
    cudaFuncSetAttribute(k_gemm2, cudaFuncAttributeMaxDynamicSharedMemorySize, (int)smem);
    cudaFuncSetAttribute(k_fused, cudaFuncAttributeMaxDynamicSharedMemorySize, (int)smem);

    cudaMemsetAsync(d_out, 0, (size_t)out_size * sizeof(float));

    // ---- packing preamble (pre-splits everything into bf16 hi/lo pairs) ----
    k_pack_act<<<dim3((unsigned)((IN + 255) / 256), 2), 256>>>(
        obs, dlt, inp, inp + IN, (int)IN);
    k_pack_w<<<dim3((unsigned)((W0S + 255) / 256), 2), 256>>>(
        oW[0], dW[0], w0p, w0p + W0S, 2048, (int)W0S);
    k_pack_w<<<dim3((unsigned)((W12S + 255) / 256), 2), 256>>>(
        oW[1], dW[1], w1p, w1p + W12S, 2048, (int)W12S);
    k_pack_w<<<dim3((unsigned)((W12S + 255) / 256), 2), 256>>>(
        oW[2], dW[2], w2p, w2p + W12S, 2048, (int)W12S);
    k_pack_w<<<dim3((unsigned)((1024ull * 16384 + 255) / 256), 1), 256>>>(
        oW[3], oW[3], w3p, w3p, 16384, 1024 * 16384);
    k_transpose_wd<<<dim3(16, 1024), 256>>>(dW[3], wdtp);

    // ---- trunk layers 0-2, both trunks per launch (z = trunk) --------------
    k_gemm2<<<dim3(16, 32, 2), 256, smem>>>(inp, inp + IN, w0p, w0p + W0S,
                                            oB[0], dB[0], a0, a0 + ACT, 256, 2048, 1);
    k_gemm2<<<dim3(16, 32, 2), 256, smem>>>(a0, a0 + ACT, w1p, w1p + W12S,
                                            oB[1], dB[1], a1, a1 + ACT, 2048, 2048, 1);
    k_gemm2<<<dim3(16, 32, 2), 256, smem>>>(a1, a1 + ACT, w2p, w2p + W12S,
                                            oB[2], dB[2], a0, a0 + ACT, 2048, 2048, 1);

    // ---- fused last layer + bilinear (never materializes [4096,16384]) ----
    k_fused<<<dim3(32, 4, 32), 256, smem>>>(a0, a0 + ACT, w3p, oB[3], wdtp, dB[3],
                                            (float*)d_out);
}